// round 8
// baseline (speedup 1.0000x reference)
#include <cuda_runtime.h>
#include <cuda_bf16.h>
#include <cuda_fp16.h>
#include <math.h>
#include <stdint.h>

#define SS   64
#define CC   32
#define CIN  3
#define HH   256
#define WW   256
#define WF   129
#define SLC  274   // per-group slice stride in float2 (2192B, 16B-aligned)

// ---------------- device scratch ----------------
__device__ __half g_x1h[(size_t)SS*HH*WW*CC];          // conv1 out hi split, [s][h][w][c]
__device__ __half g_x1l[(size_t)SS*HH*WW*CC];          // conv1 out lo split
__device__ float  g_x2[(size_t)SS*CC*HH*WW];           // conv2+LRN+coswin, [s][c][h][w]
__device__ float2 g_zf[(size_t)SS*CC*WF*HH];           // row-rfft, [s][c][k][h]
__device__ float2 g_ghat[(size_t)SS*WF*HH];            // after ifft along H, [s][k][h]
__device__ float2 g_wft[(size_t)WF*CC*HH];             // wf transposed [k][c][hf]
__device__ float2 g_tw[256];                           // e^{-2pi i m/256}
__device__ __half g_w2h[288*32];                       // [k=tap*32+ci][co] fp16

__device__ __forceinline__ uint32_t smem_u32(const void* p) {
    uint32_t a;
    asm("{ .reg .u64 t; cvta.to.shared.u64 t, %1; cvt.u32.u64 %0, t; }" : "=r"(a) : "l"(p));
    return a;
}

__device__ __forceinline__ void ldsm_x4(uint32_t* r, uint32_t addr){
    asm volatile("ldmatrix.sync.aligned.m8n8.x4.shared.b16 {%0,%1,%2,%3}, [%4];"
        : "=r"(r[0]),"=r"(r[1]),"=r"(r[2]),"=r"(r[3]) : "r"(addr));
}
__device__ __forceinline__ void ldsm_x4t(uint32_t* r, uint32_t addr){
    asm volatile("ldmatrix.sync.aligned.m8n8.x4.trans.shared.b16 {%0,%1,%2,%3}, [%4];"
        : "=r"(r[0]),"=r"(r[1]),"=r"(r[2]),"=r"(r[3]) : "r"(addr));
}
__device__ __forceinline__ void mma16816h(float* d, const uint32_t* a, const uint32_t* b){
    asm volatile("mma.sync.aligned.m16n8k16.row.col.f32.f16.f16.f32 "
        "{%0,%1,%2,%3}, {%4,%5,%6,%7}, {%8,%9}, {%0,%1,%2,%3};"
        : "+f"(d[0]), "+f"(d[1]), "+f"(d[2]), "+f"(d[3])
        : "r"(a[0]), "r"(a[1]), "r"(a[2]), "r"(a[3]), "r"(b[0]), "r"(b[1]));
}

// ================= register FFT-256 (16 threads x 16 values) =================
template<bool INV>
__device__ __forceinline__ void dft16(float2* v){
    constexpr float C1 = 0.923879532511286756f;
    constexpr float S1 = 0.382683432365089772f;
    constexpr float R2 = 0.707106781186547524f;
    const float WR[10] = {1.f,  C1,  R2,  S1, 0.f, -S1, -R2, -C1, -1.f, -C1};
    const float WI[10] = {0.f, -S1, -R2, -C1, -1.f, -C1, -R2, -S1, 0.f,  S1};
    float2 c[16];
    #pragma unroll
    for (int r = 0; r < 4; r++){
        float2 a0=v[r], a1=v[r+4], a2=v[r+8], a3=v[r+12];
        float2 t0=make_float2(a0.x+a2.x, a0.y+a2.y);
        float2 t1=make_float2(a0.x-a2.x, a0.y-a2.y);
        float2 t2=make_float2(a1.x+a3.x, a1.y+a3.y);
        float2 t3=make_float2(a1.x-a3.x, a1.y-a3.y);
        float2 j3 = INV ? make_float2(-t3.y, t3.x) : make_float2(t3.y, -t3.x);
        c[r]    = make_float2(t0.x+t2.x, t0.y+t2.y);
        c[4+r]  = make_float2(t1.x+j3.x, t1.y+j3.y);
        c[8+r]  = make_float2(t0.x-t2.x, t0.y-t2.y);
        c[12+r] = make_float2(t1.x-j3.x, t1.y-j3.y);
    }
    #pragma unroll
    for (int q = 0; q < 4; q++){
        float2 b0 = c[q*4+0], b1, b2, b3;
        {   int e = q;   float cr=WR[e], ci = INV ? -WI[e] : WI[e];
            float2 a=c[q*4+1]; b1=make_float2(a.x*cr-a.y*ci, a.x*ci+a.y*cr); }
        {   int e = 2*q; float cr=WR[e], ci = INV ? -WI[e] : WI[e];
            float2 a=c[q*4+2]; b2=make_float2(a.x*cr-a.y*ci, a.x*ci+a.y*cr); }
        {   int e = 3*q; float cr=WR[e], ci = INV ? -WI[e] : WI[e];
            float2 a=c[q*4+3]; b3=make_float2(a.x*cr-a.y*ci, a.x*ci+a.y*cr); }
        float2 t0=make_float2(b0.x+b2.x, b0.y+b2.y);
        float2 t1=make_float2(b0.x-b2.x, b0.y-b2.y);
        float2 t2=make_float2(b1.x+b3.x, b1.y+b3.y);
        float2 t3=make_float2(b1.x-b3.x, b1.y-b3.y);
        float2 j3 = INV ? make_float2(-t3.y, t3.x) : make_float2(t3.y, -t3.x);
        v[q]    = make_float2(t0.x+t2.x, t0.y+t2.y);
        v[q+4]  = make_float2(t1.x+j3.x, t1.y+j3.y);
        v[q+8]  = make_float2(t0.x-t2.x, t0.y-t2.y);
        v[q+12] = make_float2(t1.x-j3.x, t1.y-j3.y);
    }
}

template<bool INV>
__device__ __forceinline__ void fft256r(float2* v, float2* slice, int t){
    dft16<INV>(v);
    float2 base = g_tw[t];
    if (INV) base.y = -base.y;
    float2 cur = base;
    #pragma unroll
    for (int k1 = 1; k1 < 16; k1++){
        float2 a = v[k1];
        v[k1] = make_float2(a.x*cur.x - a.y*cur.y, a.x*cur.y + a.y*cur.x);
        if (k1 < 15)
            cur = make_float2(cur.x*base.x - cur.y*base.y, cur.x*base.y + cur.y*base.x);
    }
    __syncwarp();
    #pragma unroll
    for (int k1 = 0; k1 < 16; k1++) slice[k1*17 + t] = v[k1];
    __syncwarp();
    #pragma unroll
    for (int n2 = 0; n2 < 16; n2++) v[n2] = slice[t*17 + n2];
    dft16<INV>(v);
}

// ---------------- init: twiddles + wf transpose + fp16 weights ----------------
__global__ void k_init(const float* __restrict__ wf, const float* __restrict__ w2){
    int tid = blockIdx.x * blockDim.x + threadIdx.x;
    int stride = gridDim.x * blockDim.x;
    if (tid < 256) {
        double ang = -6.283185307179586476925286766559 * (double)tid / 256.0;
        g_tw[tid] = make_float2((float)cos(ang), (float)sin(ang));
    }
    for (int i = tid; i < 288*32; i += stride) {
        int k  = i >> 5, co = i & 31;
        int tap = k >> 5, ci = k & 31;
        int kh = tap / 3, kw = tap % 3;
        g_w2h[i] = __float2half(w2[((co*32 + ci)*3 + kh)*3 + kw]);
    }
    int total = WF*CC*HH;
    for (int i = tid; i < total; i += stride) {
        int hf = i & 255;
        int c  = (i >> 8) & 31;
        int k  = i >> 13;
        const float* p = wf + (((size_t)c*HH + hf)*WF + k)*2;
        g_wft[i] = make_float2(p[0], p[1]);
    }
}

// ---------------- conv1 + relu -> split fp16, [s][h][w][c] ----------------
__global__ void k_conv1(const float* __restrict__ z, const float* __restrict__ w1,
                        const float* __restrict__ b1){
    __shared__ float sIn[3*10*34];
    __shared__ float sW[27*32];
    int s  = blockIdx.z;
    int w0 = blockIdx.x * 32, h0 = blockIdx.y * 8;
    int tid = threadIdx.x;

    for (int i = tid; i < 27*32; i += 256)
        sW[i] = w1[(size_t)(i & 31)*27 + (i >> 5)];
    for (int i = tid; i < 3*10*34; i += 256) {
        int ci = i / 340, rem = i % 340, rr = rem / 34, cc = rem % 34;
        int gh = h0 + rr - 1, gw = w0 + cc - 1;
        float v = 0.f;
        if (gh >= 0 && gh < HH && gw >= 0 && gw < WW)
            v = z[(((size_t)s*CIN + ci)*HH + gh)*WW + gw];
        sIn[i] = v;
    }
    __syncthreads();

    int wg = tid & 7, r = (tid >> 3) & 7, cob = tid >> 6;
    int co0 = cob * 8;
    float acc[4][8];
    #pragma unroll
    for (int i = 0; i < 4; i++)
        #pragma unroll
        for (int j = 0; j < 8; j++) acc[i][j] = b1[co0 + j];

    #pragma unroll
    for (int ci = 0; ci < 3; ci++)
      #pragma unroll
      for (int kh = 0; kh < 3; kh++) {
        const float* rowp = &sIn[(ci*10 + r + kh)*34];
        #pragma unroll
        for (int kw = 0; kw < 3; kw++) {
            float x0 = rowp[wg      + kw];
            float x1 = rowp[wg + 8  + kw];
            float x2 = rowp[wg + 16 + kw];
            float x3 = rowp[wg + 24 + kw];
            const float* wp = &sW[((ci*3 + kh)*3 + kw)*32 + co0];
            #pragma unroll
            for (int j = 0; j < 8; j++) {
                float wv = wp[j];
                acc[0][j] += x0*wv; acc[1][j] += x1*wv;
                acc[2][j] += x2*wv; acc[3][j] += x3*wv;
            }
        }
      }

    int hh = h0 + r;
    #pragma unroll
    for (int i = 0; i < 4; i++) {
        int ww = w0 + wg + 8*i;
        size_t base = (((size_t)s*HH + hh)*WW + ww)*CC + co0;
        #pragma unroll
        for (int j = 0; j < 8; j++) {
            float v = acc[i][j];
            v = v > 0.f ? v : 0.f;
            __half hi = __float2half(v);
            g_x1h[base + j] = hi;
            g_x1l[base + j] = __float2half(v - __half2float(hi));
        }
    }
}

// ---------------- conv2 via mma.sync fp16 (2-product split, K split over 2 warpgroups) ----------------
// dynamic smem layout (bytes):
//  [0, 18432)       B image, 288 k-rows x 64B (XOR-swizzled 16B units)
//  [18432, 31488)   raw halo tile hi: 204 rows (6h x 34w) x 64B (swizzled)
//  [31488, 44544)   raw halo tile lo
//  [44544, 60928)   sOut: 32 co x 128 px floats
//  [60928, 61056)   bias
#define RAWH_OFF 18432u
#define RAWL_OFF 31488u
#define OUT_OFF  44544u
#define BIAS_OFF 60928u
#define SMEM2_BYTES 61056

__global__ void __launch_bounds__(256, 2)
k_conv2mma(const float* __restrict__ b2, const float* __restrict__ coswin){
    extern __shared__ __align__(16) uint8_t smem[];
    uint32_t sb = smem_u32(smem);
    float* sOut  = (float*)(smem + OUT_OFF);
    float* sBias = (float*)(smem + BIAS_OFF);

    const int tid = threadIdx.x;
    const int wid = tid >> 5, lane = tid & 31;
    const int grp = wid >> 2;            // 0: steps 0-8, 1: steps 9-17
    const int hl  = wid & 3;             // h row within tile
    const int s  = blockIdx.z;
    const int h0 = blockIdx.y * 4, w0 = blockIdx.x * 32;

    if (tid < 32) sBias[tid] = b2[tid];

    const uint4* wsrc = (const uint4*)g_w2h;
    for (int u = tid; u < 1152; u += 256) {
        int k  = u >> 2, nc = u & 3;
        uint32_t p = (uint32_t)(k*4 + (nc ^ ((k>>1)&3)));
        *(uint4*)(smem + p*16) = wsrc[u];
    }

    for (int u = tid; u < 816; u += 256) {
        int rawrow = u >> 2, c = u & 3;
        int hr = rawrow / 34, wc = rawrow % 34;
        int gh = h0 - 1 + hr, gw = w0 - 1 + wc;
        uint4 vh = make_uint4(0,0,0,0), vl = make_uint4(0,0,0,0);
        if (gh >= 0 && gh < HH && gw >= 0 && gw < WW) {
            size_t gi = ((size_t)((s*HH + gh))*WW + gw)*4 + c;
            vh = ((const uint4*)g_x1h)[gi];
            vl = ((const uint4*)g_x1l)[gi];
        }
        uint32_t p = (uint32_t)(rawrow*4 + (c ^ ((rawrow>>1)&3)));
        *(uint4*)(smem + RAWH_OFF + p*16) = vh;
        *(uint4*)(smem + RAWL_OFF + p*16) = vl;
    }
    __syncthreads();

    const int t15 = lane & 15;
    const int tHi = lane >> 4;
    const int swb = (t15 >> 1) & 3;

    uint32_t bA[2];
    #pragma unroll
    for (int nbx = 0; nbx < 2; nbx++)
        bA[nbx] = sb + (uint32_t)((t15*4 + ((nbx*2 + tHi) ^ swb))*16);

    float d[2][4][4];
    #pragma unroll
    for (int mb = 0; mb < 2; mb++)
        #pragma unroll
        for (int j = 0; j < 4; j++)
            #pragma unroll
            for (int e = 0; e < 4; e++) d[mb][j][e] = 0.f;

    #pragma unroll
    for (int i = 0; i < 9; i++) {
        const int st  = grp*9 + i;
        const int tap = st >> 1, kh = tap/3, kw = tap - kh*3;
        const int c0  = (st & 1) * 2;

        uint32_t ah[2][4], al[2][4];
        #pragma unroll
        for (int mb = 0; mb < 2; mb++) {
            int rawrow = (hl + kh)*34 + kw + mb*16 + t15;
            int cc = c0 + tHi;
            uint32_t p = (uint32_t)(rawrow*4 + (cc ^ ((rawrow>>1)&3)));
            ldsm_x4(ah[mb], sb + RAWH_OFF + p*16);
            ldsm_x4(al[mb], sb + RAWL_OFF + p*16);
        }
        uint32_t wh[8];
        ldsm_x4t(wh,     bA[0] + (uint32_t)st*1024u);
        ldsm_x4t(wh + 4, bA[1] + (uint32_t)st*1024u);

        #pragma unroll
        for (int mb = 0; mb < 2; mb++)
            #pragma unroll
            for (int j = 0; j < 4; j++) {
                mma16816h(d[mb][j], ah[mb], wh + 2*j);
                mma16816h(d[mb][j], al[mb], wh + 2*j);
            }
    }

    if (grp == 0) {
        #pragma unroll
        for (int mb = 0; mb < 2; mb++) {
            int px = hl*32 + mb*16 + (lane >> 2);
            #pragma unroll
            for (int j = 0; j < 4; j++) {
                int co = j*8 + (lane & 3)*2;
                sOut[co*128 + px]         = d[mb][j][0] + sBias[co];
                sOut[(co+1)*128 + px]     = d[mb][j][1] + sBias[co+1];
                sOut[co*128 + px + 8]     = d[mb][j][2] + sBias[co];
                sOut[(co+1)*128 + px + 8] = d[mb][j][3] + sBias[co+1];
            }
        }
    }
    __syncthreads();
    if (grp == 1) {
        #pragma unroll
        for (int mb = 0; mb < 2; mb++) {
            int px = hl*32 + mb*16 + (lane >> 2);
            #pragma unroll
            for (int j = 0; j < 4; j++) {
                int co = j*8 + (lane & 3)*2;
                sOut[co*128 + px]         += d[mb][j][0];
                sOut[(co+1)*128 + px]     += d[mb][j][1];
                sOut[co*128 + px + 8]     += d[mb][j][2];
                sOut[(co+1)*128 + px + 8] += d[mb][j][3];
            }
        }
    }
    __syncthreads();

    if (tid < 128) {
        int px = tid;
        int hh = h0 + (px >> 5), ww = w0 + (px & 31);
        float yv[32];
        #pragma unroll
        for (int c = 0; c < 32; c++) yv[c] = sOut[c*128 + px];
        float cw = coswin[(size_t)hh*WW + ww];
        float win = yv[0]*yv[0] + yv[1]*yv[1] + yv[2]*yv[2];
        size_t obase = ((size_t)s*CC*HH + (size_t)hh)*WW + ww;
        #pragma unroll
        for (int c = 0; c < 32; c++) {
            float t = 1.0f + 2e-5f * win;
            float v = yv[c] * __powf(t, -0.75f) * cw;
            g_x2[obase + (size_t)c*HH*WW] = v;
            if (c + 3 < 32) win += yv[c+3]*yv[c+3];
            if (c - 2 >= 0) win -= yv[c-2]*yv[c-2];
        }
    }
}

// ---------------- stage A: row rfft (2 rows packed), register FFT ----------------
__global__ void __launch_bounds__(256)
k_fftrow(){
    __shared__ float2 sbuf[16*SLC];
    const int tid = threadIdx.x;
    const int g = tid >> 4, t = tid & 15;
    const int sc = blockIdx.y;
    const int h0 = blockIdx.x * 32;
    float2* slice = sbuf + g*SLC;

    {
        const float* ra = g_x2 + (size_t)sc*HH*WW + (size_t)(h0 + 2*g)*WW;
        const float4* ra4 = (const float4*)ra;
        const float4* rb4 = (const float4*)(ra + 256);
        float* sa = (float*)slice;
        #pragma unroll
        for (int q = 0; q < 4; q++) ((float4*)sa)[q*16 + t] = ra4[q*16 + t];
        #pragma unroll
        for (int q = 0; q < 4; q++) ((float4*)(sa + 272))[q*16 + t] = rb4[q*16 + t];
        __syncwarp();
        float2 v[16];
        #pragma unroll
        for (int j = 0; j < 16; j++)
            v[j] = make_float2(sa[16*j + t], sa[272 + 16*j + t]);
        fft256r<false>(v, slice, t);
        __syncwarp();
        #pragma unroll
        for (int j = 0; j < 16; j++) slice[t + 16*j] = v[j];
    }
    __syncthreads();

    float2* outp = g_zf + (size_t)sc*WF*HH;
    for (int i = tid; i < WF*32; i += 256) {
        int k = i >> 5, idx = i & 31;
        int p = idx >> 1, ab = idx & 1;
        const float2* Z = sbuf + p*SLC;
        float2 zk = Z[k];
        float2 zm = Z[(256 - k) & 255];
        float2 o;
        if (ab == 0)
            o = make_float2(0.5f*(zk.x + zm.x), 0.5f*(zk.y - zm.y));
        else
            o = make_float2(0.5f*(zk.y + zm.y), 0.5f*(zm.x - zk.x));
        outp[(size_t)k*HH + h0 + idx] = o;
    }
}

// ---------------- stage B: per-k FFT along H + wf product + channel-sum + iFFT ----------------
__global__ void __launch_bounds__(256, 2)
k_colprod(){
    __shared__ float2 sbuf[16*SLC];
    const int tid = threadIdx.x;
    const int g = tid >> 4, t = tid & 15;
    const int s = blockIdx.y;
    const int k = blockIdx.x * 16 + g;
    const int kc = k <= 128 ? k : 128;
    float2* slice = sbuf + g*SLC;

    float2 facc[16];
    #pragma unroll
    for (int j = 0; j < 16; j++) facc[j] = make_float2(0.f, 0.f);

    for (int c = 0; c < 32; c++) {
        const float2* base = g_zf + ((size_t)(s*CC + c)*WF + kc)*HH;
        const float4* b4 = (const float4*)base;
        __syncwarp();
        #pragma unroll
        for (int q = 0; q < 8; q++) ((float4*)slice)[q*16 + t] = b4[q*16 + t];
        __syncwarp();
        float2 v[16];
        #pragma unroll
        for (int j = 0; j < 16; j++) v[j] = slice[16*j + t];
        fft256r<false>(v, slice, t);
        const float2* wp = g_wft + ((size_t)kc*CC + c)*HH;
        #pragma unroll
        for (int j = 0; j < 16; j++) {
            float2 wv = wp[t + 16*j];
            facc[j].x += wv.x * v[j].x;
            facc[j].y -= wv.y * v[j].y;
        }
    }

    fft256r<true>(facc, slice, t);
    if (k <= 128) {
        float2* outp = g_ghat + ((size_t)s*WF + k)*HH;
        #pragma unroll
        for (int j = 0; j < 16; j++)
            outp[t + 16*j] = make_float2(facc[j].x*(1.f/256.f), facc[j].y*(1.f/256.f));
    }
}

// ---------------- stage C: irfft along W (2 rows packed), register FFT ----------------
__global__ void __launch_bounds__(256)
k_irow(float* __restrict__ out){
    __shared__ float2 sbuf[16*SLC];
    const int tid = threadIdx.x;
    const int g = tid >> 4, t = tid & 15;
    const int s = blockIdx.y;
    const int h0 = blockIdx.x * 32;
    const int ha = h0 + 2*g, hb = ha + 1;
    float2* slice = sbuf + g*SLC;

    const float2* G = g_ghat + (size_t)s*WF*HH;
    float2 v[16];
    #pragma unroll
    for (int j = 0; j < 16; j++) {
        int kk = 16*j + t;
        int srck = (kk <= 128) ? kk : (256 - kk);
        float2 a = G[(size_t)srck*HH + ha];
        float2 b = G[(size_t)srck*HH + hb];
        if (srck == 0 || srck == 128) { a.y = 0.f; b.y = 0.f; }
        if (kk <= 128) v[j] = make_float2(a.x - b.y, a.y + b.x);
        else           v[j] = make_float2(a.x + b.y, b.x - a.y);
    }
    fft256r<true>(v, slice, t);

    float* o = out + (size_t)s*HH*WW;
    #pragma unroll
    for (int j = 0; j < 16; j++) {
        int wj = t + 16*j;
        o[(size_t)ha*WW + wj] = v[j].x * (1.f/256.f);
        o[(size_t)hb*WW + wj] = v[j].y * (1.f/256.f);
    }
}

extern "C" void kernel_launch(void* const* d_in, const int* in_sizes, int n_in,
                              void* d_out, int out_size){
    const float* z    = (const float*)d_in[0];
    const float* cosw = (const float*)d_in[1];
    const float* wf   = (const float*)d_in[2];
    const float* w1   = (const float*)d_in[3];
    const float* b1   = (const float*)d_in[4];
    const float* w2   = (const float*)d_in[5];
    const float* b2   = (const float*)d_in[6];
    float* out = (float*)d_out;

    cudaFuncSetAttribute(k_conv2mma, cudaFuncAttributeMaxDynamicSharedMemorySize, SMEM2_BYTES);

    k_init<<<1024, 512>>>(wf, w2);

    dim3 gc(8, 32, SS);
    k_conv1<<<gc, 256>>>(z, w1, b1);

    dim3 gm(8, 64, SS);
    k_conv2mma<<<gm, 256, SMEM2_BYTES>>>(b2, cosw);

    dim3 ga(8, SS*CC);
    k_fftrow<<<ga, 256>>>();

    dim3 gb(9, SS);
    k_colprod<<<gb, 256>>>();

    dim3 gi(8, SS);
    k_irow<<<gi, 256>>>(out);
}